// round 9
// baseline (speedup 1.0000x reference)
#include <cuda_runtime.h>
#include <cstdint>

#define NNODES 50000
#define DIM 64
#define CAP 128          // per-node bucket capacity; deg ~ Binomial(8e5, 2e-5), mean 16
#define EPS_MSG 1e-7f
#define LOG2E 1.4426950408889634f
#define WPB 8            // warps per block in fused kernel

// Static scratch
__device__ int g_cnt[NNODES];            // per-node edge count / cursor
__device__ int g_slot[NNODES * CAP];     // per-node src lists (25.6 MB)
__device__ int g_is64;                   // edge_index dtype flag

// ---------------------------------------------------------------------------
// init: zero counters; warp 0 of block 0 probes edge_index dtype in parallel.
// int64 data: all values in [0,N). int32 read as int64: lo + hi*2^32, out of
// range unless hi==0 (~1/N per probe; 32 parallel probes => ~impossible).
// Single-warp ballot, no block barrier (avoids divergent __syncthreads).
// ---------------------------------------------------------------------------
__global__ void init_kernel(const void* __restrict__ ei, int E, int N) {
    int i = blockIdx.x * blockDim.x + threadIdx.x;
    if (i < N) g_cnt[i] = 0;
    if (blockIdx.x == 0 && threadIdx.x < 32) {
        const long long* p = (const long long*)ei;
        int probes = (2 * E < 32) ? 2 * E : 32;
        int bad = 0;
        if (threadIdx.x < probes) {
            long long v = p[threadIdx.x];
            bad = (v < 0 || v >= (long long)N);
        }
        unsigned m = __ballot_sync(0xFFFFFFFFu, bad);
        if (threadIdx.x == 0) g_is64 = (m == 0u) ? 1 : 0;
    }
}

// ---------------------------------------------------------------------------
// bucket build: claim a slot in dst's list, record src. cnt = final degree.
// 2 edges per thread, vectorized index loads.
// ---------------------------------------------------------------------------
__global__ void build_kernel(const void* __restrict__ ei, int E, int N) {
    int t = blockIdx.x * blockDim.x + threadIdx.x;
    int e = t * 2;
    if (e >= E) return;
    int d0, s0, d1, s1;
    bool two = (e + 1 < E);
    if (g_is64) {
        const long long* p = (const long long*)ei;
        if (two) {
            longlong2 dv = __ldg(reinterpret_cast<const longlong2*>(p + e));
            longlong2 sv = __ldg(reinterpret_cast<const longlong2*>(p + (long long)E + e));
            d0 = (int)dv.x; d1 = (int)dv.y;
            s0 = (int)sv.x; s1 = (int)sv.y;
        } else {
            d0 = (int)p[e]; s0 = (int)p[(long long)E + e];
            d1 = -1; s1 = -1;
        }
    } else {
        const int* p = (const int*)ei;
        if (two) {
            int2 dv = __ldg(reinterpret_cast<const int2*>(p + e));
            int2 sv = __ldg(reinterpret_cast<const int2*>(p + E + e));
            d0 = dv.x; d1 = dv.y;
            s0 = sv.x; s1 = sv.y;
        } else {
            d0 = p[e]; s0 = p[E + e];
            d1 = -1; s1 = -1;
        }
    }
    if ((unsigned)d0 < (unsigned)N && (unsigned)s0 < (unsigned)N) {
        int pos = atomicAdd(&g_cnt[d0], 1);
        if (pos < CAP) g_slot[d0 * CAP + pos] = s0;
    }
    if (two && (unsigned)d1 < (unsigned)N && (unsigned)s1 < (unsigned)N) {
        int pos = atomicAdd(&g_cnt[d1], 1);
        if (pos < CAP) g_slot[d1 * CAP + pos] = s1;
    }
}

// ---------------------------------------------------------------------------
// fused aggregate + linear: one warp per node (grid-stride), lane owns 2 chans.
//   agg_c = (Σ r·exp2(bl·r)) / (Σ exp2(bl·r)) + eps,  r = relu(x), bl = β·log2e
// (eps and the common exp factor cancel exactly in the softmax ratio).
// 8-edge chunks: both slot int4 loads then ALL 8 x-gathers issued as one batch
// (MLP=8) before any math -> ~2 exposed L2 rounds per node instead of ~4.
// Then the warp finishes out[c] = b[c] + Σ_k agg[k]·W[c][k] from smem-staged
// agg row (broadcast LDS.128) and lane-major W (conflict-free LDS.128).
// ---------------------------------------------------------------------------
__global__ void __launch_bounds__(256) fused_kernel(const float* __restrict__ x,
                                                    const float* __restrict__ beta,
                                                    const float* __restrict__ W,
                                                    const float* __restrict__ b,
                                                    float* __restrict__ out,
                                                    int N) {
    // WA[kq][l] = W[2l][4kq..4kq+3], WB[kq][l] = W[2l+1][4kq..4kq+3]
    __shared__ __align__(16) float4 WA[16][32];     // 8 KB
    __shared__ __align__(16) float4 WB[16][32];     // 8 KB
    __shared__ __align__(16) float2 aggs[WPB][32];  // 2 KB per-warp row staging

    for (int i = threadIdx.x; i < 512; i += 256) {
        int kq = i >> 5, l = i & 31;
        WA[kq][l] = __ldg(reinterpret_cast<const float4*>(W + (size_t)(2 * l) * DIM + 4 * kq));
        WB[kq][l] = __ldg(reinterpret_cast<const float4*>(W + (size_t)(2 * l + 1) * DIM + 4 * kq));
    }
    __syncthreads();

    const int wid  = threadIdx.x >> 5;
    const int lane = threadIdx.x & 31;
    const float bl  = __ldg(beta) * LOG2E;
    const float bc0 = __ldg(b + 2 * lane);
    const float bc1 = __ldg(b + 2 * lane + 1);
    const int wstride = gridDim.x * WPB;

    for (int node = blockIdx.x * WPB + wid; node < N; node += wstride) {
        int deg = g_cnt[node];
        if (deg > CAP) deg = CAP;
        const int* slots = g_slot + (size_t)node * CAP;

        float d0 = 0.f, d1 = 0.f, n0 = 0.f, n1 = 0.f;

        int i = 0;
        // main: 8-edge chunks, all loads batched before math
        for (; i + 8 <= deg; i += 8) {
            int4 sa = __ldg(reinterpret_cast<const int4*>(slots + i));
            int4 sb = __ldg(reinterpret_cast<const int4*>(slots + i + 4));
            float2 v0 = __ldg(reinterpret_cast<const float2*>(x + (size_t)sa.x * DIM) + lane);
            float2 v1 = __ldg(reinterpret_cast<const float2*>(x + (size_t)sa.y * DIM) + lane);
            float2 v2 = __ldg(reinterpret_cast<const float2*>(x + (size_t)sa.z * DIM) + lane);
            float2 v3 = __ldg(reinterpret_cast<const float2*>(x + (size_t)sa.w * DIM) + lane);
            float2 v4 = __ldg(reinterpret_cast<const float2*>(x + (size_t)sb.x * DIM) + lane);
            float2 v5 = __ldg(reinterpret_cast<const float2*>(x + (size_t)sb.y * DIM) + lane);
            float2 v6 = __ldg(reinterpret_cast<const float2*>(x + (size_t)sb.z * DIM) + lane);
            float2 v7 = __ldg(reinterpret_cast<const float2*>(x + (size_t)sb.w * DIM) + lane);

#define ACC2(v)                                                   \
            {                                                     \
                float r0 = fmaxf((v).x, 0.f), r1 = fmaxf((v).y, 0.f); \
                float t0 = exp2f(bl * r0),    t1 = exp2f(bl * r1);    \
                d0 += t0; d1 += t1;                               \
                n0 = fmaf(r0, t0, n0); n1 = fmaf(r1, t1, n1);     \
            }
            ACC2(v0) ACC2(v1) ACC2(v2) ACC2(v3)
            ACC2(v4) ACC2(v5) ACC2(v6) ACC2(v7)
        }
        // 4-edge chunk
        if (i + 4 <= deg) {
            int4 s = __ldg(reinterpret_cast<const int4*>(slots + i));
            float2 v0 = __ldg(reinterpret_cast<const float2*>(x + (size_t)s.x * DIM) + lane);
            float2 v1 = __ldg(reinterpret_cast<const float2*>(x + (size_t)s.y * DIM) + lane);
            float2 v2 = __ldg(reinterpret_cast<const float2*>(x + (size_t)s.z * DIM) + lane);
            float2 v3 = __ldg(reinterpret_cast<const float2*>(x + (size_t)s.w * DIM) + lane);
            ACC2(v0) ACC2(v1) ACC2(v2) ACC2(v3)
            i += 4;
        }
        // scalar tail
        for (; i < deg; i++) {
            int s0 = __ldg(slots + i);
            float2 v = __ldg(reinterpret_cast<const float2*>(x + (size_t)s0 * DIM) + lane);
            ACC2(v)
        }
#undef ACC2

        float2 o;
        if (deg > 0) {
            o.x = n0 / d0 + EPS_MSG;   // d>0 guaranteed: exp2 > 0
            o.y = n1 / d1 + EPS_MSG;
        } else {
            o.x = 0.f; o.y = 0.f;      // empty segment -> agg = 0 (matches reference)
        }

        aggs[wid][lane] = o;
        __syncwarp();

        float acc0 = bc0, acc1 = bc1;
#pragma unroll
        for (int kq = 0; kq < 16; kq++) {
            float4 a  = *reinterpret_cast<const float4*>(&aggs[wid][2 * kq]);  // broadcast
            float4 wa = WA[kq][lane];
            float4 wb = WB[kq][lane];
            acc0 = fmaf(a.x, wa.x, acc0); acc0 = fmaf(a.y, wa.y, acc0);
            acc0 = fmaf(a.z, wa.z, acc0); acc0 = fmaf(a.w, wa.w, acc0);
            acc1 = fmaf(a.x, wb.x, acc1); acc1 = fmaf(a.y, wb.y, acc1);
            acc1 = fmaf(a.z, wb.z, acc1); acc1 = fmaf(a.w, wb.w, acc1);
        }

        float2 ov; ov.x = acc0; ov.y = acc1;
        *(reinterpret_cast<float2*>(out + (size_t)node * DIM) + lane) = ov;
        __syncwarp();   // protect aggs before next iteration overwrites it
    }
}

// ---------------------------------------------------------------------------
extern "C" void kernel_launch(void* const* d_in, const int* in_sizes, int n_in,
                              void* d_out, int out_size) {
    // Map inputs by element count (robust to metadata ordering)
    const float* x    = nullptr;
    const void*  ei   = nullptr;
    const float* W    = nullptr;
    const float* b    = nullptr;
    const float* beta = nullptr;
    int x_sz = 0, ei_sz = 0;
    for (int i = 0; i < n_in; i++) {
        int s = in_sizes[i];
        if (s == 1)               beta = (const float*)d_in[i];
        else if (s == 64)         b    = (const float*)d_in[i];
        else if (s == 64 * 64)    W    = (const float*)d_in[i];
        else if (s == out_size)   { x  = (const float*)d_in[i]; x_sz = s; }
        else                      { ei = d_in[i]; ei_sz = s; }
    }
    float* out = (float*)d_out;

    const int N = x_sz / DIM;    // 50000
    const int E = ei_sz / 2;     // 800000

    init_kernel<<<(N + 255) / 256, 256>>>(ei, E, N);
    build_kernel<<<(E / 2 + 255) / 256, 256>>>(ei, E, N);
    fused_kernel<<<740, 256>>>(x, beta, W, b, out, N);
}